// round 9
// baseline (speedup 1.0000x reference)
#include <cuda_runtime.h>
#include <cstdint>

// ---------------- problem constants ----------------
#define BB   32
#define CI_  128
#define CO_  128
#define HH   56
#define WW   56
#define HW   3136          // 56*56
#define PADW 58            // padded x
#define PADH 60            // padded y (extra rows for tail-tile garbage reads)

#define MTILE 128          // flattened pixels per CTA
#define NTILES 25          // ceil(3136/128) (tail half-masked)

// max smem A row actually addressed: row_pq(max 188) + du(max 118) = 306
#define AROWS 307
#define ABYTES (AROWS * 128)        // 39296
#define BBYTES (CO_ * 128)          // 16384 per buffer
#define SMEM_CONV (ABYTES + 2 * BBYTES)   // 72064  -> 3 CTAs/SM

// ---------------- scratch (device globals; no runtime alloc) ----------------
// both stored PRE-ROUNDED to tf32 bit patterns
__device__ float g_W2 [(size_t)BB * 9 * CO_ * CI_];        // [b][tap][co][ci]
__device__ float g_pad[(size_t)BB * PADH * PADW * CI_];    // [b][y][x][ci]

// ---------------- helpers ----------------
__device__ __forceinline__ uint32_t smem_to_u32(const void* p) {
    uint32_t a;
    asm("{ .reg .u64 t; cvta.to.shared.u64 t, %1; cvt.u32.u64 %0, t; }" : "=r"(a) : "l"(p));
    return a;
}
__device__ __forceinline__ uint32_t f32_to_tf32(float f) {
    uint32_t r; asm("cvt.rna.tf32.f32 %0, %1;" : "=r"(r) : "f"(f)); return r;
}
__device__ __forceinline__ void ldsm_x4(uint32_t* r, uint32_t addr) {
    asm volatile("ldmatrix.sync.aligned.m8n8.x4.shared.b16 {%0,%1,%2,%3}, [%4];"
        : "=r"(r[0]), "=r"(r[1]), "=r"(r[2]), "=r"(r[3]) : "r"(addr));
}
__device__ __forceinline__ void mma_tf32(float* c, const uint32_t* a, const uint32_t* b) {
    asm volatile("mma.sync.aligned.m16n8k8.row.col.f32.tf32.tf32.f32 "
        "{%0,%1,%2,%3}, {%4,%5,%6,%7}, {%8,%9}, {%0,%1,%2,%3};"
        : "+f"(c[0]), "+f"(c[1]), "+f"(c[2]), "+f"(c[3])
        : "r"(a[0]), "r"(a[1]), "r"(a[2]), "r"(a[3]), "r"(b[0]), "r"(b[1]));
}
__device__ __forceinline__ void cp16(uint32_t dst, const void* src) {
    asm volatile("cp.async.cg.shared.global [%0], [%1], 16;" :: "r"(dst), "l"(src));
}
#define CP_COMMIT() asm volatile("cp.async.commit_group;" ::: "memory")
#define CP_WAIT0()  asm volatile("cp.async.wait_group 0;" ::: "memory")

// ---------------------------------------------------------------------------
// prep W (fused): g_W2[b][tap][co][ci] = tf32(eps[b][co][ci*9+tap]*exp(psi)+mu)
// ---------------------------------------------------------------------------
__global__ void prepw_kernel(const float* __restrict__ eps,
                             const float* __restrict__ psi,
                             const float* __restrict__ mu) {
    int ci = threadIdx.x;
    int co = blockIdx.x, b = blockIdx.y;
    const float* e = eps + ((size_t)(b * CO_ + co) * CI_ + ci) * 9;
    const float* p = psi + ((size_t)co * CI_ + ci) * 9;
    const float* m = mu  + ((size_t)co * CI_ + ci) * 9;
    float v[9];
#pragma unroll
    for (int k = 0; k < 9; k++)
        v[k] = fmaf(e[k], __expf(p[k]), m[k]);
#pragma unroll
    for (int k = 0; k < 9; k++)
        g_W2[((size_t)(b * 9 + k) * CO_ + co) * CI_ + ci] = __uint_as_float(f32_to_tf32(v[k]));
}

// ---------------------------------------------------------------------------
// NCHW -> padded NHWC (tf32-prerounded) + border zeroing folded in.
// grid (98, 4, 32), block (32, 8).
// ---------------------------------------------------------------------------
__global__ void intrans_kernel(const float* __restrict__ in) {
    __shared__ float t[32][33];
    int b = blockIdx.z, hw0 = blockIdx.x * 32, ci0 = blockIdx.y * 32;
    int tx = threadIdx.x, ty = threadIdx.y;
    int tid = ty * 32 + tx;

    // border zeroing: 32*344*32 = 352256 float4 slots over first 1376 blocks
    int blin = (blockIdx.z * gridDim.y + blockIdx.y) * gridDim.x + blockIdx.x;
    if (blin < 1376) {
        int gi = blin * 256 + tid;
        int bz = gi / (344 * 32);
        int r  = gi % (344 * 32);
        int pi = r >> 5, f = r & 31;
        int y, x;
        if (pi < 58)       { y = 0;  x = pi; }
        else if (pi < 116) { y = 57; x = pi - 58; }
        else if (pi < 174) { y = 58; x = pi - 116; }
        else if (pi < 232) { y = 59; x = pi - 174; }
        else if (pi < 288) { y = pi - 232 + 1; x = 0; }
        else               { y = pi - 288 + 1; x = 57; }
        ((float4*)g_pad)[(((size_t)bz * PADH + y) * PADW + x) * 32 + f] =
            make_float4(0.f, 0.f, 0.f, 0.f);
    }

    const float* ib = in + (size_t)b * CI_ * HW;
#pragma unroll
    for (int j = 0; j < 32; j += 8)
        t[ty + j][tx] = ib[(size_t)(ci0 + ty + j) * HW + hw0 + tx];
    __syncthreads();
#pragma unroll
    for (int j = 0; j < 32; j += 8) {
        int hw = hw0 + ty + j;
        int y = hw / WW, x = hw - y * WW;
        g_pad[(((size_t)b * PADH + y + 1) * PADW + (x + 1)) * CI_ + ci0 + tx] =
            __uint_as_float(f32_to_tf32(t[tx][ty + j]));
    }
}

// ---------------------------------------------------------------------------
// conv: implicit GEMM, mma.sync tf32, cp.async staging.
// CTA = 128 flattened pixels x 128 co, warp grid 2(M) x 4(N).
// A staged once per ci-chunk (307-row halo, exact bound). B double-buffered,
// one barrier per tap. 3 CTAs/SM (72 KB smem, 85-reg cap).
// grid (25, 32), block 256.
// ---------------------------------------------------------------------------
__global__ __launch_bounds__(256, 3) void conv_mma(float* __restrict__ out) {
    extern __shared__ __align__(128) char smem[];
    uint32_t As_u = smem_to_u32(smem);
    uint32_t Bs_u = As_u + ABYTES;

    int tid = threadIdx.x, lid = tid & 31, wid = tid >> 5;
    int tile = blockIdx.x, b = blockIdx.y;
    int m_w = wid >> 2;                 // 0..1  (M half)
    int n_w = wid & 3;                  // 0..3  (N quarter)

    int p0   = tile * MTILE;
    int y_lo = p0 / WW;

    const float* apage = g_pad + (((size_t)b * PADH + y_lo) * PADW) * CI_;
    const float* wpage = g_W2 + (size_t)b * 9 * CO_ * CI_;

    // ---- fragment lane addressing ----
    int rA    = lid & 7;
    int add8A = ((lid >> 3) & 1) << 3;
    int jAh   = lid >> 4;               // A k-block half
    int jBh   = (lid >> 3) & 1;         // B k-block half
    int rowB  = n_w * 32 + (((lid >> 4) & 1) << 3) + rA;
    uint32_t b_base  = Bs_u + (uint32_t)rowB * 128;
    uint32_t xorB_sh = (uint32_t)rA << 4;

    // per-lane pixel -> halo-row base for this warp's 4 m-frags (u=0,v=0)
    int row_pq[4];
#pragma unroll
    for (int mf = 0; mf < 4; mf++) {
        int p  = p0 + (m_w * 4 + mf) * 16 + rA + add8A;
        int y  = p / WW;
        row_pq[mf] = (y - y_lo) * PADW + (p - y * WW);
    }

    float acc[4][4][4];
#pragma unroll
    for (int mf = 0; mf < 4; mf++)
#pragma unroll
        for (int nn = 0; nn < 4; nn++)
#pragma unroll
            for (int q = 0; q < 4; q++) acc[mf][nn][q] = 0.f;

    int buf = 0;
    for (int cc = 0; cc < 4; cc++) {
        int ccol = cc * 32;
        __syncthreads();   // previous-cc reads of As / Bs done

        // ---- stage A: 307 rows x 8 x 16B = 2456 cp16, swizzled ----
#pragma unroll
        for (int t = 0; t < 10; t++) {
            int c = tid + t * 256;
            if (t < 9 || c < AROWS * 8) {
                int q = c >> 3, j = c & 7;
                cp16(As_u + (uint32_t)(q * 128 + ((j ^ (q & 7)) << 4)),
                     apage + (size_t)q * CI_ + ccol + j * 4);
            }
        }
        // ---- stage B tap 0 into buf ----
        {
            const float* wsrc = wpage + ccol;
#pragma unroll
            for (int t = 0; t < 4; t++) {
                int c = tid + t * 256;
                int co = c >> 3, j = c & 7;
                cp16(Bs_u + (uint32_t)(buf * BBYTES + co * 128 + ((j ^ (co & 7)) << 4)),
                     wsrc + (size_t)co * CI_ + j * 4);
            }
        }
        CP_COMMIT();

        for (int uv = 0; uv < 9; uv++) {
            CP_WAIT0();
            __syncthreads();

            if (uv < 8) {   // prefetch next tap's B into other buffer
                const float* wsrc = wpage + (size_t)(uv + 1) * CO_ * CI_ + ccol;
#pragma unroll
                for (int t = 0; t < 4; t++) {
                    int c = tid + t * 256;
                    int co = c >> 3, j = c & 7;
                    cp16(Bs_u + (uint32_t)((buf ^ 1) * BBYTES + co * 128 + ((j ^ (co & 7)) << 4)),
                         wsrc + (size_t)co * CI_ + j * 4);
                }
                CP_COMMIT();
            }

            // ---- compute tap uv ----
            int u = uv / 3, v = uv - u * 3;
            int du = u * PADW + v;
            uint32_t abase[4], axsh[4];
#pragma unroll
            for (int mf = 0; mf < 4; mf++) {
                int q = row_pq[mf] + du;
                abase[mf] = As_u + (uint32_t)q * 128;
                axsh[mf]  = (uint32_t)(q & 7) << 4;
            }
            uint32_t bb = b_base + (uint32_t)buf * BBYTES;
#pragma unroll
            for (int kk = 0; kk < 4; kk++) {
                uint32_t koff = ((uint32_t)(kk * 2 + jBh)) << 4;
                uint32_t bf0[4], bf1[4];
                ldsm_x4(bf0, bb +        (koff ^ xorB_sh));          // co n_w*32 +  0..15
                ldsm_x4(bf1, bb + 2048 + (koff ^ xorB_sh));          // co n_w*32 + 16..31
                uint32_t koffA = ((uint32_t)(kk * 2 + jAh)) << 4;
#pragma unroll
                for (int mf = 0; mf < 4; mf++) {
                    uint32_t af[4];
                    ldsm_x4(af, abase[mf] + (koffA ^ axsh[mf]));
                    mma_tf32(acc[mf][0], af, bf0);
                    mma_tf32(acc[mf][1], af, bf0 + 2);
                    mma_tf32(acc[mf][2], af, bf1);
                    mma_tf32(acc[mf][3], af, bf1 + 2);
                }
            }
            buf ^= 1;
        }
    }

    // ---- epilogue: direct NCHW stores (flattened pixel index = p) ----
    float* ob = out + (size_t)b * CO_ * HW;
    int g = lid >> 2, tg = lid & 3;
#pragma unroll
    for (int mf = 0; mf < 4; mf++) {
#pragma unroll
        for (int h = 0; h < 2; h++) {
            int p = p0 + (m_w * 4 + mf) * 16 + g + 8 * h;
            if (p < HW) {
#pragma unroll
                for (int nn = 0; nn < 4; nn++) {
                    int col = n_w * 32 + nn * 8 + (tg << 1);
                    ob[(size_t)col * HW + p]       = acc[mf][nn][2 * h];
                    ob[(size_t)(col + 1) * HW + p] = acc[mf][nn][2 * h + 1];
                }
            }
        }
    }
}

// ---------------------------------------------------------------------------
extern "C" void kernel_launch(void* const* d_in, const int* in_sizes, int n_in,
                              void* d_out, int out_size) {
    const float* input = (const float*)d_in[0];   // [32,128,56,56]
    const float* eps   = (const float*)d_in[1];   // [32,128,128,3,3]
    const float* psi   = (const float*)d_in[2];   // [128,128,3,3]
    const float* mu    = (const float*)d_in[3];   // [128,128,3,3]
    float* out = (float*)d_out;                   // [32,128,56,56]

    prepw_kernel<<<dim3(CO_, BB), 128>>>(eps, psi, mu);
    intrans_kernel<<<dim3(98, 4, BB), dim3(32, 8)>>>(input);

    cudaFuncSetAttribute(conv_mma, cudaFuncAttributeMaxDynamicSharedMemorySize, SMEM_CONV);
    conv_mma<<<dim3(NTILES, BB), 256, SMEM_CONV>>>(out);
}

// round 10
// speedup vs baseline: 3.2220x; 3.2220x over previous
#include <cuda_runtime.h>
#include <cuda_fp16.h>
#include <cstdint>

// ---------------- problem constants ----------------
#define BB   32
#define CI_  128
#define CO_  128
#define HH   56
#define WW   56
#define HW   3136          // 56*56
#define PADW 58            // padded x
#define PADH 60            // padded y (extra rows for tail-tile garbage reads)

#define MTILE 128          // flattened pixels per CTA
#define NTILES 25          // ceil(3136/128) (tail half-masked)

#define AROWS 307          // exact halo bound (max smem row index 306)
#define ABYTES (AROWS * 128)        // 39296  (64 fp16 per row)
#define BBYTES (CO_ * 128)          // 16384 per buffer (128 co x 64 fp16)
#define SMEM_CONV (ABYTES + 2 * BBYTES)   // 72064

// ---------------- scratch (device globals; fp16) ----------------
__device__ __half g_W2h [(size_t)BB * 9 * CO_ * CI_];       // [b][tap][co][ci]  9.4 MB
__device__ __half g_padh[(size_t)BB * PADH * PADW * CI_];   // [b][y][x][ci]    28.5 MB

// ---------------- helpers ----------------
__device__ __forceinline__ uint32_t smem_to_u32(const void* p) {
    uint32_t a;
    asm("{ .reg .u64 t; cvta.to.shared.u64 t, %1; cvt.u32.u64 %0, t; }" : "=r"(a) : "l"(p));
    return a;
}
__device__ __forceinline__ void ldsm_x4(uint32_t* r, uint32_t addr) {
    asm volatile("ldmatrix.sync.aligned.m8n8.x4.shared.b16 {%0,%1,%2,%3}, [%4];"
        : "=r"(r[0]), "=r"(r[1]), "=r"(r[2]), "=r"(r[3]) : "r"(addr));
}
__device__ __forceinline__ void mma_fp16(float* c, const uint32_t* a, const uint32_t* b) {
    asm volatile("mma.sync.aligned.m16n8k16.row.col.f32.f16.f16.f32 "
        "{%0,%1,%2,%3}, {%4,%5,%6,%7}, {%8,%9}, {%0,%1,%2,%3};"
        : "+f"(c[0]), "+f"(c[1]), "+f"(c[2]), "+f"(c[3])
        : "r"(a[0]), "r"(a[1]), "r"(a[2]), "r"(a[3]), "r"(b[0]), "r"(b[1]));
}
__device__ __forceinline__ void cp16(uint32_t dst, const void* src) {
    asm volatile("cp.async.cg.shared.global [%0], [%1], 16;" :: "r"(dst), "l"(src));
}
#define CP_COMMIT() asm volatile("cp.async.commit_group;" ::: "memory")
#define CP_WAIT0()  asm volatile("cp.async.wait_group 0;" ::: "memory")

// ---------------------------------------------------------------------------
// prep W: g_W2h[b][tap][co][ci] = fp16(eps[b][co][ci*9+tap]*exp(psi)+mu)
// grid (CO_, BB), block 128 (thread = ci)
// ---------------------------------------------------------------------------
__global__ void prepw_kernel(const float* __restrict__ eps,
                             const float* __restrict__ psi,
                             const float* __restrict__ mu) {
    int ci = threadIdx.x;
    int co = blockIdx.x, b = blockIdx.y;
    const float* e = eps + ((size_t)(b * CO_ + co) * CI_ + ci) * 9;
    const float* p = psi + ((size_t)co * CI_ + ci) * 9;
    const float* m = mu  + ((size_t)co * CI_ + ci) * 9;
    float v[9];
#pragma unroll
    for (int k = 0; k < 9; k++)
        v[k] = fmaf(e[k], __expf(p[k]), m[k]);
#pragma unroll
    for (int k = 0; k < 9; k++)
        g_W2h[((size_t)(b * 9 + k) * CO_ + co) * CI_ + ci] = __float2half_rn(v[k]);
}

// ---------------------------------------------------------------------------
// NCHW -> padded NHWC fp16 + border zeroing folded in.
// grid (98, 4, 32), block (32, 8).
// border: 32 b x 344 pixels x 16 float4 (256B/pixel) = 176128 slots, 688 blocks
// ---------------------------------------------------------------------------
__global__ void intrans_kernel(const float* __restrict__ in) {
    __shared__ float t[32][33];
    int b = blockIdx.z, hw0 = blockIdx.x * 32, ci0 = blockIdx.y * 32;
    int tx = threadIdx.x, ty = threadIdx.y;
    int tid = ty * 32 + tx;

    int blin = (blockIdx.z * gridDim.y + blockIdx.y) * gridDim.x + blockIdx.x;
    if (blin < 688) {
        int gi = blin * 256 + tid;
        int bz = gi / (344 * 16);
        int r  = gi % (344 * 16);
        int pi = r >> 4, f = r & 15;
        int y, x;
        if (pi < 58)       { y = 0;  x = pi; }
        else if (pi < 116) { y = 57; x = pi - 58; }
        else if (pi < 174) { y = 58; x = pi - 116; }
        else if (pi < 232) { y = 59; x = pi - 174; }
        else if (pi < 288) { y = pi - 232 + 1; x = 0; }
        else               { y = pi - 288 + 1; x = 57; }
        ((float4*)g_padh)[(((size_t)bz * PADH + y) * PADW + x) * 16 + f] =
            make_float4(0.f, 0.f, 0.f, 0.f);
    }

    const float* ib = in + (size_t)b * CI_ * HW;
#pragma unroll
    for (int j = 0; j < 32; j += 8)
        t[ty + j][tx] = ib[(size_t)(ci0 + ty + j) * HW + hw0 + tx];
    __syncthreads();
#pragma unroll
    for (int j = 0; j < 32; j += 8) {
        int hw = hw0 + ty + j;
        int y = hw / WW, x = hw - y * WW;
        g_padh[(((size_t)b * PADH + y + 1) * PADW + (x + 1)) * CI_ + ci0 + tx] =
            __float2half_rn(t[tx][ty + j]);
    }
}

// ---------------------------------------------------------------------------
// conv: implicit GEMM, mma.sync fp16 (m16n8k16), cp.async staging.
// CTA = 128 flattened pixels x 128 co, warp grid 2(M) x 4(N).
// ci in 2 chunks of 64 (one 128B smem row per pixel). A staged once per
// chunk over the 307-row halo; 9 taps read at row offset u*58+v.
// B double-buffered per tap. grid (25, 32), block 256, 2 CTAs/SM.
// ---------------------------------------------------------------------------
__global__ __launch_bounds__(256, 2) void conv_mma(float* __restrict__ out) {
    extern __shared__ __align__(128) char smem[];
    uint32_t As_u = smem_to_u32(smem);
    uint32_t Bs_u = As_u + ABYTES;

    int tid = threadIdx.x, lid = tid & 31, wid = tid >> 5;
    int tile = blockIdx.x, b = blockIdx.y;
    int m_w = wid >> 2;                 // 0..1  (M half)
    int n_w = wid & 3;                  // 0..3  (N quarter)

    int p0   = tile * MTILE;
    int y_lo = p0 / WW;

    const __half* apage = g_padh + (((size_t)b * PADH + y_lo) * PADW) * CI_;
    const __half* wpage = g_W2h + (size_t)b * 9 * CO_ * CI_;

    // ---- fragment lane addressing (identical selectors to tf32 version) ----
    int rA    = lid & 7;
    int add8A = ((lid >> 3) & 1) << 3;  // A: lanes 8-15/24-31 -> rows +8
    int jAh   = lid >> 4;               // A: lanes 16-31 -> +16B k-half
    int jBh   = (lid >> 3) & 1;         // B: lanes 8-15/24-31 -> +16B k-half
    int rowB  = n_w * 32 + (((lid >> 4) & 1) << 3) + rA;   // lanes16-31 -> co +8
    uint32_t b_base  = Bs_u + (uint32_t)rowB * 128;
    uint32_t xorB_sh = (uint32_t)rA << 4;

    // per-lane pixel -> halo-row base for this warp's 4 m-frags
    int row_pq[4];
#pragma unroll
    for (int mf = 0; mf < 4; mf++) {
        int p  = p0 + (m_w * 4 + mf) * 16 + rA + add8A;
        int y  = p / WW;
        row_pq[mf] = (y - y_lo) * PADW + (p - y * WW);
    }

    float acc[4][4][4];
#pragma unroll
    for (int mf = 0; mf < 4; mf++)
#pragma unroll
        for (int nn = 0; nn < 4; nn++)
#pragma unroll
            for (int q = 0; q < 4; q++) acc[mf][nn][q] = 0.f;

    int buf = 0;
    for (int cc = 0; cc < 2; cc++) {
        int ccol = cc * 64;            // fp16 element offset within ci
        __syncthreads();               // previous-chunk reads done

        // ---- stage A: 307 rows x 8 x 16B = 2456 cp16, swizzled ----
#pragma unroll
        for (int t = 0; t < 10; t++) {
            int c = tid + t * 256;
            if (t < 9 || c < AROWS * 8) {
                int q = c >> 3, j = c & 7;   // j: 16B unit (8 fp16)
                cp16(As_u + (uint32_t)(q * 128 + ((j ^ (q & 7)) << 4)),
                     apage + (size_t)q * CI_ + ccol + j * 8);
            }
        }
        // ---- stage B tap 0 into buf ----
        {
            const __half* wsrc = wpage + ccol;
#pragma unroll
            for (int t = 0; t < 4; t++) {
                int c = tid + t * 256;
                int co = c >> 3, j = c & 7;
                cp16(Bs_u + (uint32_t)(buf * BBYTES + co * 128 + ((j ^ (co & 7)) << 4)),
                     wsrc + (size_t)co * CI_ + j * 8);
            }
        }
        CP_COMMIT();

        for (int uv = 0; uv < 9; uv++) {
            CP_WAIT0();
            __syncthreads();

            if (uv < 8) {   // prefetch next tap's B into other buffer
                const __half* wsrc = wpage + (size_t)(uv + 1) * CO_ * CI_ + ccol;
#pragma unroll
                for (int t = 0; t < 4; t++) {
                    int c = tid + t * 256;
                    int co = c >> 3, j = c & 7;
                    cp16(Bs_u + (uint32_t)((buf ^ 1) * BBYTES + co * 128 + ((j ^ (co & 7)) << 4)),
                         wsrc + (size_t)co * CI_ + j * 8);
                }
                CP_COMMIT();
            }

            // ---- compute tap uv: 4 k-steps of 16 ----
            int u = uv / 3, v = uv - u * 3;
            int du = u * PADW + v;
            uint32_t abase[4], axsh[4];
#pragma unroll
            for (int mf = 0; mf < 4; mf++) {
                int q = row_pq[mf] + du;
                abase[mf] = As_u + (uint32_t)q * 128;
                axsh[mf]  = (uint32_t)(q & 7) << 4;
            }
            uint32_t bb = b_base + (uint32_t)buf * BBYTES;
#pragma unroll
            for (int kk = 0; kk < 4; kk++) {
                uint32_t koffB = (uint32_t)(kk * 32 + jBh * 16);
                uint32_t bf0[4], bf1[4];
                ldsm_x4(bf0, bb +        (koffB ^ xorB_sh));   // co n_w*32 +  0..15
                ldsm_x4(bf1, bb + 2048 + (koffB ^ xorB_sh));   // co n_w*32 + 16..31
                uint32_t koffA = (uint32_t)(kk * 32 + jAh * 16);
#pragma unroll
                for (int mf = 0; mf < 4; mf++) {
                    uint32_t af[4];
                    ldsm_x4(af, abase[mf] + (koffA ^ axsh[mf]));
                    mma_fp16(acc[mf][0], af, bf0);        // co  0-7
                    mma_fp16(acc[mf][1], af, bf0 + 2);    // co  8-15
                    mma_fp16(acc[mf][2], af, bf1);        // co 16-23
                    mma_fp16(acc[mf][3], af, bf1 + 2);    // co 24-31
                }
            }
            buf ^= 1;
        }
    }

    // ---- epilogue: direct NCHW stores (flattened pixel index = p) ----
    float* ob = out + (size_t)b * CO_ * HW;
    int g = lid >> 2, tg = lid & 3;
#pragma unroll
    for (int mf = 0; mf < 4; mf++) {
#pragma unroll
        for (int h = 0; h < 2; h++) {
            int p = p0 + (m_w * 4 + mf) * 16 + g + 8 * h;
            if (p < HW) {
#pragma unroll
                for (int nn = 0; nn < 4; nn++) {
                    int col = n_w * 32 + nn * 8 + (tg << 1);
                    ob[(size_t)col * HW + p]       = acc[mf][nn][2 * h];
                    ob[(size_t)(col + 1) * HW + p] = acc[mf][nn][2 * h + 1];
                }
            }
        }
    }
}

// ---------------------------------------------------------------------------
extern "C" void kernel_launch(void* const* d_in, const int* in_sizes, int n_in,
                              void* d_out, int out_size) {
    const float* input = (const float*)d_in[0];   // [32,128,56,56]
    const float* eps   = (const float*)d_in[1];   // [32,128,128,3,3]
    const float* psi   = (const float*)d_in[2];   // [128,128,3,3]
    const float* mu    = (const float*)d_in[3];   // [128,128,3,3]
    float* out = (float*)d_out;                   // [32,128,56,56]

    prepw_kernel<<<dim3(CO_, BB), 128>>>(eps, psi, mu);
    intrans_kernel<<<dim3(98, 4, BB), dim3(32, 8)>>>(input);

    cudaFuncSetAttribute(conv_mma, cudaFuncAttributeMaxDynamicSharedMemorySize, SMEM_CONV);
    conv_mma<<<dim3(NTILES, BB), 256, SMEM_CONV>>>(out);
}

// round 11
// speedup vs baseline: 3.5703x; 1.1081x over previous
#include <cuda_runtime.h>
#include <cuda_fp16.h>
#include <cstdint>

// ---------------- problem constants ----------------
#define BB   32
#define CI_  128
#define CO_  128
#define HH   56
#define WW   56
#define HW   3136          // 56*56
#define PADW 58            // padded x
#define PADH 60            // padded y (extra rows for tail-tile garbage reads)

#define MTILE 128          // flattened pixels per CTA
#define NTILES 25          // ceil(3136/128) (tail half-masked)

#define AROWS 307          // exact halo bound (max smem row index 306)
#define ABYTES (AROWS * 128)        // 39296  (64 fp16 per row)
#define BBYTES (CO_ * 128)          // 16384 per buffer (128 co x 64 fp16)
#define NBUF   4
#define SMEM_CONV (ABYTES + NBUF * BBYTES)   // 104832 -> 2 CTAs/SM

#define PREPW_BLOCKS  2048          // 2 co per block
#define INTRANS_BLOCKS (98 * 4 * 32)

// ---------------- scratch (device globals; fp16) ----------------
__device__ __half g_W2h [(size_t)BB * 9 * CO_ * CI_];       // [b][tap][co][ci]
__device__ __half g_padh[(size_t)BB * PADH * PADW * CI_];   // [b][y][x][ci]

// ---------------- helpers ----------------
__device__ __forceinline__ uint32_t smem_to_u32(const void* p) {
    uint32_t a;
    asm("{ .reg .u64 t; cvta.to.shared.u64 t, %1; cvt.u32.u64 %0, t; }" : "=r"(a) : "l"(p));
    return a;
}
__device__ __forceinline__ void ldsm_x4(uint32_t* r, uint32_t addr) {
    asm volatile("ldmatrix.sync.aligned.m8n8.x4.shared.b16 {%0,%1,%2,%3}, [%4];"
        : "=r"(r[0]), "=r"(r[1]), "=r"(r[2]), "=r"(r[3]) : "r"(addr));
}
__device__ __forceinline__ void mma_fp16(float* c, const uint32_t* a, const uint32_t* b) {
    asm volatile("mma.sync.aligned.m16n8k16.row.col.f32.f16.f16.f32 "
        "{%0,%1,%2,%3}, {%4,%5,%6,%7}, {%8,%9}, {%0,%1,%2,%3};"
        : "+f"(c[0]), "+f"(c[1]), "+f"(c[2]), "+f"(c[3])
        : "r"(a[0]), "r"(a[1]), "r"(a[2]), "r"(a[3]), "r"(b[0]), "r"(b[1]));
}
__device__ __forceinline__ void cp16(uint32_t dst, const void* src) {
    asm volatile("cp.async.cg.shared.global [%0], [%1], 16;" :: "r"(dst), "l"(src));
}
#define CP_COMMIT() asm volatile("cp.async.commit_group;" ::: "memory")
#define CP_WAIT0()  asm volatile("cp.async.wait_group 0;" ::: "memory")

// ---------------------------------------------------------------------------
// fused prep: block < PREPW_BLOCKS   -> weight reparam+transpose (2 co/block)
//             block >= PREPW_BLOCKS  -> input NCHW -> padded NHWC fp16
//                                       (+ border zeroing in first 688 blocks)
// 256 threads.
// ---------------------------------------------------------------------------
__global__ __launch_bounds__(256) void prep_all(const float* __restrict__ in,
                                                const float* __restrict__ eps,
                                                const float* __restrict__ psi,
                                                const float* __restrict__ mu) {
    __shared__ float t[32][33];
    int blk = blockIdx.x;
    int tid = threadIdx.x;

    if (blk < PREPW_BLOCKS) {
        // ---- weights: b = blk/64, co = (blk%64)*2 + tid/128, ci = tid%128 ----
        int b  = blk >> 6;
        int co = ((blk & 63) << 1) + (tid >> 7);
        int ci = tid & 127;
        const float* e = eps + ((size_t)(b * CO_ + co) * CI_ + ci) * 9;
        const float* p = psi + ((size_t)co * CI_ + ci) * 9;
        const float* m = mu  + ((size_t)co * CI_ + ci) * 9;
        float v[9];
#pragma unroll
        for (int k = 0; k < 9; k++)
            v[k] = fmaf(e[k], __expf(p[k]), m[k]);
#pragma unroll
        for (int k = 0; k < 9; k++)
            g_W2h[((size_t)(b * 9 + k) * CO_ + co) * CI_ + ci] = __float2half_rn(v[k]);
        return;
    }

    int blk2 = blk - PREPW_BLOCKS;
    // ---- border zeroing: 32 b x 344 pixels x 16 float4 over first 688 blocks ----
    if (blk2 < 688) {
        int gi = blk2 * 256 + tid;
        int bz = gi / (344 * 16);
        int r  = gi % (344 * 16);
        int pi = r >> 4, f = r & 15;
        int y, x;
        if (pi < 58)       { y = 0;  x = pi; }
        else if (pi < 116) { y = 57; x = pi - 58; }
        else if (pi < 174) { y = 58; x = pi - 116; }
        else if (pi < 232) { y = 59; x = pi - 174; }
        else if (pi < 288) { y = pi - 232 + 1; x = 0; }
        else               { y = pi - 288 + 1; x = 57; }
        ((float4*)g_padh)[(((size_t)bz * PADH + y) * PADW + x) * 16 + f] =
            make_float4(0.f, 0.f, 0.f, 0.f);
    }

    // ---- input transpose: emulate grid (98, 4, 32), block (32, 8) ----
    int bx = blk2 % 98;
    int rem = blk2 / 98;
    int by = rem & 3;
    int bz = rem >> 2;
    int tx = tid & 31, ty = tid >> 5;
    int b = bz, hw0 = bx * 32, ci0 = by * 32;

    const float* ib = in + (size_t)b * CI_ * HW;
#pragma unroll
    for (int j = 0; j < 32; j += 8)
        t[ty + j][tx] = ib[(size_t)(ci0 + ty + j) * HW + hw0 + tx];
    __syncthreads();
#pragma unroll
    for (int j = 0; j < 32; j += 8) {
        int hw = hw0 + ty + j;
        int y = hw / WW, x = hw - y * WW;
        g_padh[(((size_t)b * PADH + y + 1) * PADW + (x + 1)) * CI_ + ci0 + tx] =
            __float2half_rn(t[tx][ty + j]);
    }
}

// ---------------------------------------------------------------------------
// conv: implicit GEMM, mma.sync fp16 (m16n8k16), cp.async staging.
// CTA = 128 flattened pixels x 128 co, warp grid 2(M) x 4(N).
// ci in 2 chunks of 64. A staged once per chunk (307-row halo).
// B quad-buffered (buffer = tap & 3): one barrier per TWO taps; the tap pair
// runs in a non-unrolled runtime loop so the window body stays ~1 tap of code.
// grid (25, 32), block 256, 2 CTAs/SM.
// ---------------------------------------------------------------------------
__global__ __launch_bounds__(256, 2) void conv_mma(float* __restrict__ out) {
    extern __shared__ __align__(128) char smem[];
    uint32_t As_u = smem_to_u32(smem);
    uint32_t Bs_u = As_u + ABYTES;

    int tid = threadIdx.x, lid = tid & 31, wid = tid >> 5;
    int tile = blockIdx.x, b = blockIdx.y;
    int m_w = wid >> 2;                 // 0..1  (M half)
    int n_w = wid & 3;                  // 0..3  (N quarter)

    int p0   = tile * MTILE;
    int y_lo = p0 / WW;

    const __half* apage = g_padh + (((size_t)b * PADH + y_lo) * PADW) * CI_;
    const __half* wpage = g_W2h + (size_t)b * 9 * CO_ * CI_;

    // ---- fragment lane addressing ----
    int rA    = lid & 7;
    int add8A = ((lid >> 3) & 1) << 3;
    int jAh   = lid >> 4;               // A +16B k-half
    int jBh   = (lid >> 3) & 1;         // B +16B k-half
    int rowB  = n_w * 32 + (((lid >> 4) & 1) << 3) + rA;
    uint32_t b_base  = Bs_u + (uint32_t)rowB * 128;
    uint32_t xorB_sh = (uint32_t)rA << 4;

    int row_pq[4];
#pragma unroll
    for (int mf = 0; mf < 4; mf++) {
        int p  = p0 + (m_w * 4 + mf) * 16 + rA + add8A;
        int y  = p / WW;
        row_pq[mf] = (y - y_lo) * PADW + (p - y * WW);
    }

    float acc[4][4][4];
#pragma unroll
    for (int mf = 0; mf < 4; mf++)
#pragma unroll
        for (int nn = 0; nn < 4; nn++)
#pragma unroll
            for (int q = 0; q < 4; q++) acc[mf][nn][q] = 0.f;

    auto stageB = [&](int uv, int ccol) {
        const __half* wsrc = wpage + (size_t)uv * CO_ * CI_ + ccol;
        uint32_t dstb = Bs_u + (uint32_t)((uv & 3) * BBYTES);
#pragma unroll
        for (int t = 0; t < 4; t++) {
            int c = tid + t * 256;
            int co = c >> 3, j = c & 7;
            cp16(dstb + (uint32_t)(co * 128 + ((j ^ (co & 7)) << 4)),
                 wsrc + (size_t)co * CI_ + j * 8);
        }
    };
    auto computeTap = [&](int uv) {
        int u = uv / 3, v = uv - u * 3;
        int du = u * PADW + v;
        uint32_t abase[4], axsh[4];
#pragma unroll
        for (int mf = 0; mf < 4; mf++) {
            int q = row_pq[mf] + du;
            abase[mf] = As_u + (uint32_t)q * 128;
            axsh[mf]  = (uint32_t)(q & 7) << 4;
        }
        uint32_t bb = b_base + (uint32_t)((uv & 3) * BBYTES);
#pragma unroll
        for (int kk = 0; kk < 4; kk++) {
            uint32_t koffB = (uint32_t)(kk * 32 + jBh * 16);
            uint32_t bf0[4], bf1[4];
            ldsm_x4(bf0, bb +        (koffB ^ xorB_sh));
            ldsm_x4(bf1, bb + 2048 + (koffB ^ xorB_sh));
            uint32_t koffA = (uint32_t)(kk * 32 + jAh * 16);
#pragma unroll
            for (int mf = 0; mf < 4; mf++) {
                uint32_t af[4];
                ldsm_x4(af, abase[mf] + (koffA ^ axsh[mf]));
                mma_fp16(acc[mf][0], af, bf0);
                mma_fp16(acc[mf][1], af, bf0 + 2);
                mma_fp16(acc[mf][2], af, bf1);
                mma_fp16(acc[mf][3], af, bf1 + 2);
            }
        }
    };

    for (int cc = 0; cc < 2; cc++) {
        int ccol = cc * 64;            // fp16 element offset within ci
        __syncthreads();               // previous-chunk reads done

        // ---- stage A: 307 rows x 8 x 16B, swizzled ----
#pragma unroll
        for (int t = 0; t < 10; t++) {
            int c = tid + t * 256;
            if (t < 9 || c < AROWS * 8) {
                int q = c >> 3, j = c & 7;
                cp16(As_u + (uint32_t)(q * 128 + ((j ^ (q & 7)) << 4)),
                     apage + (size_t)q * CI_ + ccol + j * 8);
            }
        }
        // ---- stage B taps 0,1 ----
        stageB(0, ccol);
        stageB(1, ccol);
        CP_COMMIT();

        // window loop: taps w2, w2+1; prefetch w2+2, w2+3
#pragma unroll 1
        for (int w2 = 0; w2 < 9; w2 += 2) {
            CP_WAIT0();
            __syncthreads();
            if (w2 + 2 < 9) {
                stageB(w2 + 2, ccol);
                if (w2 + 3 < 9) stageB(w2 + 3, ccol);
                CP_COMMIT();
            }
#pragma unroll 1
            for (int t = 0; t < 2; t++) {
                int uv = w2 + t;
                if (uv < 9) computeTap(uv);
            }
        }
    }

    // ---- epilogue: direct NCHW stores ----
    float* ob = out + (size_t)b * CO_ * HW;
    int g = lid >> 2, tg = lid & 3;
#pragma unroll
    for (int mf = 0; mf < 4; mf++) {
#pragma unroll
        for (int h = 0; h < 2; h++) {
            int p = p0 + (m_w * 4 + mf) * 16 + g + 8 * h;
            if (p < HW) {
#pragma unroll
                for (int nn = 0; nn < 4; nn++) {
                    int col = n_w * 32 + nn * 8 + (tg << 1);
                    ob[(size_t)col * HW + p]       = acc[mf][nn][2 * h];
                    ob[(size_t)(col + 1) * HW + p] = acc[mf][nn][2 * h + 1];
                }
            }
        }
    }
}

// ---------------------------------------------------------------------------
extern "C" void kernel_launch(void* const* d_in, const int* in_sizes, int n_in,
                              void* d_out, int out_size) {
    const float* input = (const float*)d_in[0];   // [32,128,56,56]
    const float* eps   = (const float*)d_in[1];   // [32,128,128,3,3]
    const float* psi   = (const float*)d_in[2];   // [128,128,3,3]
    const float* mu    = (const float*)d_in[3];   // [128,128,3,3]
    float* out = (float*)d_out;                   // [32,128,56,56]

    prep_all<<<PREPW_BLOCKS + INTRANS_BLOCKS, 256>>>(input, eps, psi, mu);

    cudaFuncSetAttribute(conv_mma, cudaFuncAttributeMaxDynamicSharedMemorySize, SMEM_CONV);
    conv_mma<<<dim3(NTILES, BB), 256, SMEM_CONV>>>(out);
}